// round 6
// baseline (speedup 1.0000x reference)
#include <cuda_runtime.h>
#include <math.h>

namespace {
constexpr int kB = 8;
constexpr int kN = 4096;
constexpr int kD = 512;
constexpr int kL = 64;
constexpr int kKS = 8;                // split-k slices for qall/qk
constexpr int kKZ = 4;                // split-k slices for big gemms
constexpr int kM = kB * kL;           // 512 rows through the GEMMs
constexpr int kSlab = kM * kD;        // 262144 floats per partial slab
constexpr int kGrid = 148;            // one block per SM -> residency guaranteed
constexpr float kInvTemp = 0.044194173824159216f; // 1/sqrt(512)
}

// ---------------- scratch (device globals; no allocation allowed) ----------
__device__ int   g_order[kB * kN];
__device__ int   g_nvalid[kB];
__device__ float g_qallp[kKS * kL * kD];
__device__ float g_qkp[kKS * kL * kD];
__device__ float g_U[kM * kD];
__device__ float g_denom[kM];
__device__ float g_P1[kKZ * kSlab];
__device__ float g_Zt[kSlab];
__device__ float g_P2[kKZ * kSlab];

// grid barrier state (monotonic generation; safe across graph replays)
__device__ volatile unsigned g_barc;
__device__ volatile unsigned g_barg;

__device__ __forceinline__ void gbar() {
    __syncthreads();
    if (threadIdx.x == 0) {
        __threadfence();
        unsigned gen = g_barg;
        if (atomicAdd((unsigned*)&g_barc, 1u) == (unsigned)gridDim.x - 1u) {
            g_barc = 0;
            __threadfence();
            g_barg = gen + 1u;
        } else {
            while (g_barg == gen) { __nanosleep(64); }
        }
        __threadfence();
    }
    __syncthreads();
}

__device__ __forceinline__ float dot4(float4 a, float4 b) {
    return a.x * b.x + a.y * b.y + a.z * b.z + a.w * b.w;
}
__device__ __forceinline__ float sum4(float4 a) { return a.x + a.y + a.z + a.w; }

__device__ __forceinline__ bool mask_at(const void* m, int idx, int kind) {
    if (kind == 1) return ((const int*)m)[idx] != 0;
    if (kind == 2) return ((const float*)m)[idx] != 0.0f;
    return ((const unsigned char*)m)[idx] != 0;
}

// ---- gemm phase: 128 jobs, BM=128 BN=64 kchunk=128, BK=8 dbuf, 8x4 micro ----
__device__ __forceinline__ void gemm_phase(const float* __restrict__ A,
                                           const float* __restrict__ W,
                                           float* __restrict__ Pout,
                                           float* sp, int bid, int tid) {
    // As(buf,k,m) = sp[buf*1056 + k*132 + m]   (2*8*132 = 2112 floats)
    // Bs(buf,k,n) = sp[2112 + buf*544 + k*68 + n]
    const int nt = bid & 7, mt = (bid >> 3) & 3, kz = bid >> 5;
    const int n0 = nt * 64, m0 = mt * 128, kb = kz * 128;
    const int tx = tid & 15, ty = tid >> 4;
    const bool bact = tid < 128;

    const float* ap = A + (size_t)(m0 + (tid >> 1)) * kD + kb + (tid & 1) * 4;
    const float* bp = W + (size_t)(n0 + ((tid & 127) >> 1)) * kD + kb + (tid & 1) * 4;
    const int lrow = tid >> 1, lkq = (tid & 1) * 4;

    float4 ra = *(const float4*)ap;
    float4 rb = bact ? *(const float4*)bp : make_float4(0.f, 0.f, 0.f, 0.f);
#pragma unroll
    for (int c = 0; c < 4; c++) {
        sp[(lkq + c) * 132 + lrow] = ((const float*)&ra)[c];
        if (bact) sp[2112 + (lkq + c) * 68 + ((tid & 127) >> 1)] = ((const float*)&rb)[c];
    }
    __syncthreads();

    float acc[8][4] = {};
    int cur = 0;
#pragma unroll 1
    for (int s = 0; s < 16; s++) {
        if (s < 15) {
            ra = *(const float4*)(ap + (s + 1) * 8);
            if (bact) rb = *(const float4*)(bp + (s + 1) * 8);
        }
        const float* Ab = sp + cur * 1056;
        const float* Bb = sp + 2112 + cur * 544;
#pragma unroll
        for (int k = 0; k < 8; k++) {
            float4 a0 = *(const float4*)&Ab[k * 132 + ty * 8];
            float4 a1 = *(const float4*)&Ab[k * 132 + ty * 8 + 4];
            float4 bv = *(const float4*)&Bb[k * 68 + tx * 4];
            const float* apv = (const float*)&a0;
            const float* aqv = (const float*)&a1;
#pragma unroll
            for (int i = 0; i < 4; i++) {
                acc[i][0] += apv[i] * bv.x; acc[i][1] += apv[i] * bv.y;
                acc[i][2] += apv[i] * bv.z; acc[i][3] += apv[i] * bv.w;
                acc[i + 4][0] += aqv[i] * bv.x; acc[i + 4][1] += aqv[i] * bv.y;
                acc[i + 4][2] += aqv[i] * bv.z; acc[i + 4][3] += aqv[i] * bv.w;
            }
        }
        if (s < 15) {
            const int nxt = cur ^ 1;
            float* An = sp + nxt * 1056;
            float* Bn = sp + 2112 + nxt * 544;
#pragma unroll
            for (int c = 0; c < 4; c++) {
                An[(lkq + c) * 132 + lrow] = ((const float*)&ra)[c];
                if (bact) Bn[(lkq + c) * 68 + ((tid & 127) >> 1)] = ((const float*)&rb)[c];
            }
            __syncthreads();
            cur = nxt;
        }
    }

    float* base = Pout + (size_t)kz * kSlab;
#pragma unroll
    for (int i = 0; i < 8; i++) {
        const int m = m0 + ty * 8 + i;
        float4 v = make_float4(acc[i][0], acc[i][1], acc[i][2], acc[i][3]);
        *(float4*)(base + (size_t)m * kD + n0 + tx * 4) = v;
    }
}

// =========================== THE mega-kernel ================================
__global__ __launch_bounds__(256) void mega_k(const void* __restrict__ mask,
                                              const float* __restrict__ z,
                                              const float* __restrict__ Wq,
                                              const float* __restrict__ Wk,
                                              const float* __restrict__ feats,
                                              const float* __restrict__ Wv,
                                              const float* __restrict__ Wo,
                                              const float* __restrict__ bo,
                                              float* __restrict__ out) {
    __shared__ __align__(16) float sp[8704];   // 34.8 KB phase-shared pool
    const int bid = blockIdx.x;
    const int tid = threadIdx.x;
    const int wid = tid >> 5, lane = tid & 31;

    // ---------------- P0: order (blocks 0..7) + qall tiles (8..71) ----------
    if (bid < kB) {
        const int b = bid;
        const unsigned* mw = (const unsigned*)mask;
        int iok = 1, fok = 1;
        for (int i = tid; i < 1024; i += 256) {
            unsigned v = mw[b * 1024 + i];
            iok &= (v <= 1u);
            fok &= (v == 0u || v == 0x3F800000u);
        }
        iok = __syncthreads_and(iok);
        fok = __syncthreads_and(fok);
        const int kind = iok ? 1 : (fok ? 2 : 0);

        const int base = tid * 16;
        bool v[16];
        int c = 0;
#pragma unroll
        for (int j = 0; j < 16; j++) {
            v[j] = !mask_at(mask, b * kN + base + j, kind);
            c += v[j] ? 1 : 0;
        }
        int inc = c;
#pragma unroll
        for (int o = 1; o < 32; o <<= 1) {
            int x = __shfl_up_sync(0xffffffffu, inc, o);
            if (lane >= o) inc += x;
        }
        __shared__ int wsum[8], woff[8];
        if (lane == 31) wsum[wid] = inc;
        __syncthreads();
        if (tid < 8) {
            int s = 0;
            for (int w = 0; w < 8; w++) { woff[w] = s; s += wsum[w]; }
            if (tid == 0) g_nvalid[b] = s;
        }
        __syncthreads();
        int pos = woff[wid] + inc - c;
#pragma unroll
        for (int j = 0; j < 16; j++) {
            if (v[j]) g_order[b * kN + pos++] = base + j;
        }
    } else if (bid < kB + 64) {
        const int bid2 = bid - kB;
        const int nt = bid2 & 7, kz = bid2 >> 3;
        const int kb = kz * 64;
        // Asm(k,l)=sp[k*68+l]; Bsm(k,d)=sp[4352+k*68+d]
        for (int jj = tid; jj < 1024; jj += 256) {
            const int l = jj >> 4, k4 = (jj & 15) * 4;
            float4 v = *(const float4*)(z + (size_t)l * kD + kb + k4);
            sp[(k4 + 0) * 68 + l] = v.x; sp[(k4 + 1) * 68 + l] = v.y;
            sp[(k4 + 2) * 68 + l] = v.z; sp[(k4 + 3) * 68 + l] = v.w;
        }
        for (int jj = tid; jj < 1024; jj += 256) {
            const int d = jj >> 4, k4 = (jj & 15) * 4;
            float4 v = *(const float4*)(Wq + (size_t)(nt * 64 + d) * kD + kb + k4);
            sp[4352 + (k4 + 0) * 68 + d] = v.x; sp[4352 + (k4 + 1) * 68 + d] = v.y;
            sp[4352 + (k4 + 2) * 68 + d] = v.z; sp[4352 + (k4 + 3) * 68 + d] = v.w;
        }
        __syncthreads();
        const int tx = tid & 15, ty = tid >> 4;
        float acc[4][4] = {};
#pragma unroll 4
        for (int k = 0; k < 64; k++) {
            float4 a = *(const float4*)&sp[k * 68 + ty * 4];
            float4 b = *(const float4*)&sp[4352 + k * 68 + tx * 4];
            acc[0][0] += a.x * b.x; acc[0][1] += a.x * b.y; acc[0][2] += a.x * b.z; acc[0][3] += a.x * b.w;
            acc[1][0] += a.y * b.x; acc[1][1] += a.y * b.y; acc[1][2] += a.y * b.z; acc[1][3] += a.y * b.w;
            acc[2][0] += a.z * b.x; acc[2][1] += a.z * b.y; acc[2][2] += a.z * b.z; acc[2][3] += a.z * b.w;
            acc[3][0] += a.w * b.x; acc[3][1] += a.w * b.y; acc[3][2] += a.w * b.z; acc[3][3] += a.w * b.w;
        }
#pragma unroll
        for (int i = 0; i < 4; i++) {
            float4 v = make_float4(acc[i][0], acc[i][1], acc[i][2], acc[i][3]);
            *(float4*)&g_qallp[(size_t)kz * (kL * kD) + (size_t)(ty * 4 + i) * kD + nt * 64 + tx * 4] = v;
        }
    }
    gbar();

    // ---------------- P1: qk tiles (blocks 0..63) ---------------------------
    if (bid < 64) {
        const int nt = bid & 7, kz = bid >> 3;
        const int kb = kz * 64;
        for (int jj = tid; jj < 1024; jj += 256) {
            const int l = jj >> 4, k4 = (jj & 15) * 4;
            float4 v = make_float4(0.f, 0.f, 0.f, 0.f);
#pragma unroll
            for (int s = 0; s < kKS; s++) {
                float4 p = *(const float4*)&g_qallp[(size_t)s * (kL * kD) + (size_t)l * kD + kb + k4];
                v.x += p.x; v.y += p.y; v.z += p.z; v.w += p.w;
            }
            sp[(k4 + 0) * 68 + l] = v.x; sp[(k4 + 1) * 68 + l] = v.y;
            sp[(k4 + 2) * 68 + l] = v.z; sp[(k4 + 3) * 68 + l] = v.w;
        }
        for (int jj = tid; jj < 1024; jj += 256) {
            const int k = jj >> 4, e4 = (jj & 15) * 4;
            float4 v = *(const float4*)(Wk + (size_t)(kb + k) * kD + nt * 64 + e4);
            *(float4*)&sp[4352 + k * 68 + e4] = v;
        }
        __syncthreads();
        const int tx = tid & 15, ty = tid >> 4;
        float acc[4][4] = {};
#pragma unroll 4
        for (int k = 0; k < 64; k++) {
            float4 a = *(const float4*)&sp[k * 68 + ty * 4];
            float4 b = *(const float4*)&sp[4352 + k * 68 + tx * 4];
            acc[0][0] += a.x * b.x; acc[0][1] += a.x * b.y; acc[0][2] += a.x * b.z; acc[0][3] += a.x * b.w;
            acc[1][0] += a.y * b.x; acc[1][1] += a.y * b.y; acc[1][2] += a.y * b.z; acc[1][3] += a.y * b.w;
            acc[2][0] += a.z * b.x; acc[2][1] += a.z * b.y; acc[2][2] += a.z * b.z; acc[2][3] += a.z * b.w;
            acc[3][0] += a.w * b.x; acc[3][1] += a.w * b.y; acc[3][2] += a.w * b.z; acc[3][3] += a.w * b.w;
        }
#pragma unroll
        for (int i = 0; i < 4; i++) {
            float4 v = make_float4(acc[i][0], acc[i][1], acc[i][2], acc[i][3]);
            *(float4*)&g_qkp[(size_t)(kz * kL + ty * 4 + i) * kD + nt * 64 + tx * 4] = v;
        }
    }
    gbar();

    // ---------------- P2: attention (blocks 0..127, 4 pairs x 2 warps) ------
    // pool: qk_s4 = sp[0..2047]; s_part(w,e) = sp[2048 + w*512 + e]; den = sp[6144+w]
    if (bid < 128) {
        for (int e = tid; e < 2048; e += 256) {
            const int s = e >> 9;
            const int l = (bid * 4 + s) & 63;
            float acc = 0.f;
#pragma unroll
            for (int ks = 0; ks < kKS; ks++)
                acc += g_qkp[(size_t)(ks * kL + l) * kD + (e & 511)];
            sp[e] = acc;
        }
        __syncthreads();

        const int slot = wid >> 1, sub = wid & 1;
        const int p = bid * 4 + slot;
        const int b = p >> 6;

        float4 qk4[4];
        float qks = 0.f;
#pragma unroll
        for (int q = 0; q < 4; q++) {
            qk4[q] = *(const float4*)&sp[slot * 512 + (lane + 32 * q) * 4];
            qks += sum4(qk4[q]);
        }
#pragma unroll
        for (int o = 16; o; o >>= 1) qks += __shfl_xor_sync(0xffffffffu, qks, o);

        const int nv = g_nvalid[b];
        int segsz = nv / kL; if (segsz < 1) segsz = 1;
        const int n_used = min(nv, kL * segsz);
        const int t0 = (p & 63) * segsz;
        const int t1 = min(t0 + segsz, n_used);

        float4 sac[4];
#pragma unroll
        for (int q = 0; q < 4; q++) sac[q] = make_float4(0.f, 0.f, 0.f, 0.f);
        float dac = 0.f;

        int t = t0 + sub;
        int o_cur = (t < t1) ? g_order[b * kN + t] : 0;
        int o_nxt = (t + 2 < t1) ? g_order[b * kN + t + 2] : 0;
        float4 v[4];
        if (t < t1) {
            const float4* row = (const float4*)(feats + ((size_t)b * kN + o_cur) * kD);
#pragma unroll
            for (int q = 0; q < 4; q++) v[q] = row[lane + 32 * q];
        }
        for (; t < t1; t += 2) {
            const int tn = t + 2;
            float4 vn[4];
            if (tn < t1) {
                const float4* rown = (const float4*)(feats + ((size_t)b * kN + o_nxt) * kD);
#pragma unroll
                for (int q = 0; q < 4; q++) vn[q] = rown[lane + 32 * q];
            }
            const int o_n2 = (tn + 2 < t1) ? g_order[b * kN + tn + 2] : 0;

            float sm = 0.f, sq = 0.f, dt = 0.f;
#pragma unroll
            for (int q = 0; q < 4; q++) {
                sm += sum4(v[q]);
                sq += dot4(v[q], v[q]);
                dt += dot4(v[q], qk4[q]);
            }
#pragma unroll
            for (int o = 16; o; o >>= 1) {
                sm += __shfl_xor_sync(0xffffffffu, sm, o);
                sq += __shfl_xor_sync(0xffffffffu, sq, o);
                dt += __shfl_xor_sync(0xffffffffu, dt, o);
            }
            const float mu = sm * (1.0f / kD);
            const float var = sq * (1.0f / kD) - mu * mu;
            const float rstd = rsqrtf(var + 1e-5f);
            float logit = (dt - mu * qks) * rstd * kInvTemp;
            logit = fminf(5.0f, fmaxf(-5.0f, logit));
            const float w = __expf(logit - 5.0f);
            const float wr = w * rstd;
            const float wm = wr * mu;
#pragma unroll
            for (int q = 0; q < 4; q++) {
                sac[q].x += wr * v[q].x - wm;
                sac[q].y += wr * v[q].y - wm;
                sac[q].z += wr * v[q].z - wm;
                sac[q].w += wr * v[q].w - wm;
            }
            dac += w;
#pragma unroll
            for (int q = 0; q < 4; q++) v[q] = vn[q];
            o_nxt = o_n2;
        }

#pragma unroll
        for (int q = 0; q < 4; q++)
            *(float4*)&sp[2048 + wid * 512 + (lane + 32 * q) * 4] = sac[q];
        if (lane == 0) sp[6144 + wid] = dac;
        __syncthreads();

#pragma unroll
        for (int s2 = 0; s2 < 4; s2++) {
            const int m = bid * 4 + s2;
            const float den = sp[6144 + 2 * s2] + sp[6144 + 2 * s2 + 1];
            const float inv = (den > 0.f) ? (1.0f / den) : 0.f;
            for (int e = tid; e < kD; e += 256) {
                const float sv = sp[2048 + 2 * s2 * 512 + e] + sp[2048 + (2 * s2 + 1) * 512 + e];
                g_U[(size_t)m * kD + e] = sv * inv;
            }
            if (tid == 0) g_denom[m] = den;
        }
    }
    gbar();

    // ---------------- P3: gemm1 (U @ Wv^T -> P1 slabs) -----------------------
    if (bid < 128) gemm_phase(g_U, Wv, g_P1, sp, bid, tid);
    gbar();

    // ---------------- P4: reduce P1 -> Zt (+ empty-seg replacement) ----------
    for (int idx = bid * 256 + tid; idx < kSlab / 4; idx += kGrid * 256) {
        const int m = idx >> 7, c4 = idx & 127;
        float4 v;
        if (g_denom[m] > 0.f) {
            v = make_float4(0.f, 0.f, 0.f, 0.f);
#pragma unroll
            for (int s = 0; s < kKZ; s++) {
                float4 pp = ((const float4*)g_P1)[(size_t)s * (kSlab / 4) + idx];
                v.x += pp.x; v.y += pp.y; v.z += pp.z; v.w += pp.w;
            }
        } else {
            v = ((const float4*)(z + (size_t)(m & (kL - 1)) * kD))[c4];
        }
        ((float4*)g_Zt)[idx] = v;
    }
    gbar();

    // ---------------- P5: gemm2 (Zt @ Wo^T -> P2 slabs) ----------------------
    if (bid < 128) gemm_phase(g_Zt, Wo, g_P2, sp, bid, tid);
    gbar();

    // ---------------- P6: final reduce + bias + sample replacement ----------
    for (int idx = bid * 256 + tid; idx < kSlab / 4; idx += kGrid * 256) {
        const int m = idx >> 7, c4 = idx & 127;
        float4 v;
        if (g_nvalid[m >> 6] == 0) {
            v = ((const float4*)(z + (size_t)(m & (kL - 1)) * kD))[c4];
        } else {
            v = ((const float4*)bo)[c4];
#pragma unroll
            for (int s = 0; s < kKZ; s++) {
                float4 pp = ((const float4*)g_P2)[(size_t)s * (kSlab / 4) + idx];
                v.x += pp.x; v.y += pp.y; v.z += pp.z; v.w += pp.w;
            }
        }
        ((float4*)out)[idx] = v;
    }
}

// ---------------------------------------------------------------------------
extern "C" void kernel_launch(void* const* d_in, const int* in_sizes, int n_in,
                              void* d_out, int out_size) {
    (void)in_sizes; (void)n_in; (void)out_size;
    const float* feats = (const float*)d_in[0];
    // d_in[1] = coords (unused by the reference output)
    const void*  mask  = d_in[2];
    const float* z     = (const float*)d_in[3];
    const float* Wq    = (const float*)d_in[4];
    const float* Wk    = (const float*)d_in[5];
    const float* Wv    = (const float*)d_in[6];
    const float* Wo    = (const float*)d_in[7];
    const float* bo    = (const float*)d_in[8];
    float* out = (float*)d_out;

    mega_k<<<kGrid, 256>>>(mask, z, Wq, Wk, feats, Wv, Wo, bo, out);
}

// round 8
// speedup vs baseline: 1.1780x; 1.1780x over previous
#include <cuda_runtime.h>
#include <cuda_bf16.h>
#include <math.h>
#include <stdint.h>

namespace {
constexpr int kB = 8;
constexpr int kN = 4096;
constexpr int kD = 512;
constexpr int kL = 64;
constexpr int kKS = 8;                // split-k slices for qall/qk
constexpr int kM = kB * kL;           // 512 rows through the GEMMs
constexpr float kInvTemp = 0.044194173824159216f; // 1/sqrt(512)
}

// ---------------- scratch (device globals; no allocation allowed) ----------
__device__ int   g_order[kB * kN];
__device__ int   g_nvalid[kB];
__device__ float g_qallp[kKS * kL * kD];
__device__ float g_qkp[kKS * kL * kD];
__device__ float g_denom[kM];
__device__ __nv_bfloat16 g_Uh[kM * kD],  g_Ul[kM * kD];   // bf16 split of U
__device__ __nv_bfloat16 g_Wvh[kD * kD], g_Wvl[kD * kD];
__device__ __nv_bfloat16 g_Woh[kD * kD], g_Wol[kD * kD];
__device__ __nv_bfloat16 g_Zh[kM * kD],  g_Zl[kM * kD];   // bf16 split of Zattn

__device__ __forceinline__ float dot4(float4 a, float4 b) {
    return a.x * b.x + a.y * b.y + a.z * b.z + a.w * b.w;
}
__device__ __forceinline__ float sum4(float4 a) { return a.x + a.y + a.z + a.w; }

__device__ __forceinline__ bool mask_at(const void* m, int idx, int kind) {
    if (kind == 1) return ((const int*)m)[idx] != 0;
    if (kind == 2) return ((const float*)m)[idx] != 0.0f;
    return ((const unsigned char*)m)[idx] != 0;
}

__device__ __forceinline__ uint32_t s2u(const void* p) {
    uint32_t a;
    asm("{ .reg .u64 t; cvta.to.shared.u64 t, %1; cvt.u32.u64 %0, t; }"
        : "=r"(a) : "l"(p));
    return a;
}
__device__ __forceinline__ void ldsm4(uint32_t addr, uint32_t r[4]) {
    asm volatile("ldmatrix.sync.aligned.m8n8.x4.shared.b16 {%0,%1,%2,%3}, [%4];"
        : "=r"(r[0]), "=r"(r[1]), "=r"(r[2]), "=r"(r[3]) : "r"(addr));
}
__device__ __forceinline__ void mma16816(float d[4], const uint32_t a[4],
                                         uint32_t b0, uint32_t b1) {
    asm volatile(
        "mma.sync.aligned.m16n8k16.row.col.f32.bf16.bf16.f32 "
        "{%0,%1,%2,%3}, {%4,%5,%6,%7}, {%8,%9}, {%0,%1,%2,%3};"
        : "+f"(d[0]), "+f"(d[1]), "+f"(d[2]), "+f"(d[3])
        : "r"(a[0]), "r"(a[1]), "r"(a[2]), "r"(a[3]), "r"(b0), "r"(b1));
}

__device__ __forceinline__ void bf16_split_store4(float4 v, __nv_bfloat16* dh,
                                                  __nv_bfloat16* dl) {
    __nv_bfloat162 h01 = __floats2bfloat162_rn(v.x, v.y);
    __nv_bfloat162 h23 = __floats2bfloat162_rn(v.z, v.w);
    float2 f01 = __bfloat1622float2(h01);
    float2 f23 = __bfloat1622float2(h23);
    __nv_bfloat162 l01 = __floats2bfloat162_rn(v.x - f01.x, v.y - f01.y);
    __nv_bfloat162 l23 = __floats2bfloat162_rn(v.z - f23.x, v.w - f23.y);
    *(__nv_bfloat162*)(dh)     = h01;
    *(__nv_bfloat162*)(dh + 2) = h23;
    *(__nv_bfloat162*)(dl)     = l01;
    *(__nv_bfloat162*)(dl + 2) = l23;
}

// ==== K1: blocks 0..7 order; 8..71 qall tiles; 72..199 weight bf16 splits ===
__global__ __launch_bounds__(256) void k1_order_qall(const void* __restrict__ mask,
                                                     const float* __restrict__ z,
                                                     const float* __restrict__ Wq,
                                                     const float* __restrict__ Wv,
                                                     const float* __restrict__ Wo) {
    const int tid = threadIdx.x;
    const int wid = tid >> 5, lane = tid & 31;

    __shared__ float Asm[64][68];
    __shared__ float Bsm[64][68];

    if (blockIdx.x < kB) {
        const int b = blockIdx.x;
        const unsigned* mw = (const unsigned*)mask;
        int iok = 1, fok = 1;
        for (int i = tid; i < 1024; i += 256) {
            unsigned v = mw[b * 1024 + i];
            iok &= (v <= 1u);
            fok &= (v == 0u || v == 0x3F800000u);
        }
        iok = __syncthreads_and(iok);
        fok = __syncthreads_and(fok);
        const int kind = iok ? 1 : (fok ? 2 : 0);

        const int base = tid * 16;
        bool v[16];
        int c = 0;
#pragma unroll
        for (int j = 0; j < 16; j++) {
            v[j] = !mask_at(mask, b * kN + base + j, kind);
            c += v[j] ? 1 : 0;
        }
        int inc = c;
#pragma unroll
        for (int o = 1; o < 32; o <<= 1) {
            int x = __shfl_up_sync(0xffffffffu, inc, o);
            if (lane >= o) inc += x;
        }
        __shared__ int wsum[8], woff[8];
        if (lane == 31) wsum[wid] = inc;
        __syncthreads();
        if (tid < 8) {
            int s = 0;
            for (int w = 0; w < 8; w++) { woff[w] = s; s += wsum[w]; }
            if (tid == 0) g_nvalid[b] = s;
        }
        __syncthreads();
        int pos = woff[wid] + inc - c;
#pragma unroll
        for (int j = 0; j < 16; j++) {
            if (v[j]) g_order[b * kN + pos++] = base + j;
        }
    } else if (blockIdx.x < kB + 64) {
        const int bid2 = blockIdx.x - kB;
        const int nt = bid2 & 7, kz = bid2 >> 3;
        const int kb = kz * 64;
        for (int jj = tid; jj < 1024; jj += 256) {
            const int l = jj >> 4, k4 = (jj & 15) * 4;
            float4 v = *(const float4*)(z + (size_t)l * kD + kb + k4);
            Asm[k4 + 0][l] = v.x; Asm[k4 + 1][l] = v.y;
            Asm[k4 + 2][l] = v.z; Asm[k4 + 3][l] = v.w;
        }
        for (int jj = tid; jj < 1024; jj += 256) {
            const int d = jj >> 4, k4 = (jj & 15) * 4;
            float4 v = *(const float4*)(Wq + (size_t)(nt * 64 + d) * kD + kb + k4);
            Bsm[k4 + 0][d] = v.x; Bsm[k4 + 1][d] = v.y;
            Bsm[k4 + 2][d] = v.z; Bsm[k4 + 3][d] = v.w;
        }
        __syncthreads();
        const int tx = tid & 15, ty = tid >> 4;
        float acc[4][4] = {};
#pragma unroll 4
        for (int k = 0; k < 64; k++) {
            float4 a = *(const float4*)&Asm[k][ty * 4];
            float4 b = *(const float4*)&Bsm[k][tx * 4];
            acc[0][0] += a.x * b.x; acc[0][1] += a.x * b.y; acc[0][2] += a.x * b.z; acc[0][3] += a.x * b.w;
            acc[1][0] += a.y * b.x; acc[1][1] += a.y * b.y; acc[1][2] += a.y * b.z; acc[1][3] += a.y * b.w;
            acc[2][0] += a.z * b.x; acc[2][1] += a.z * b.y; acc[2][2] += a.z * b.z; acc[2][3] += a.z * b.w;
            acc[3][0] += a.w * b.x; acc[3][1] += a.w * b.y; acc[3][2] += a.w * b.z; acc[3][3] += a.w * b.w;
        }
#pragma unroll
        for (int i = 0; i < 4; i++) {
            float4 v = make_float4(acc[i][0], acc[i][1], acc[i][2], acc[i][3]);
            *(float4*)&g_qallp[(size_t)kz * (kL * kD) + (size_t)(ty * 4 + i) * kD + nt * 64 + tx * 4] = v;
        }
    } else {
        // weight bf16 splits: 128 blocks; 0..63 -> Wv, 64..127 -> Wo
        const int wb = blockIdx.x - (kB + 64);
        const int which = wb >> 6, lb = wb & 63;
        const float* src = which ? Wo : Wv;
        __nv_bfloat16* dh = which ? g_Woh : g_Wvh;
        __nv_bfloat16* dl = which ? g_Wol : g_Wvl;
#pragma unroll
        for (int it = 0; it < 4; it++) {
            const int i = lb * 4096 + it * 1024 + tid * 4;
            float4 v = *(const float4*)(src + i);
            bf16_split_store4(v, dh + i, dl + i);
        }
    }
}

// ======================= K2: qk GEMM ========================================
__global__ __launch_bounds__(256) void qk_gemm(const float* __restrict__ Wk) {
    const int tid = threadIdx.x;
    const int nt = blockIdx.x & 7, kz = blockIdx.x >> 3;
    const int kb = kz * 64;
    __shared__ float Asm[64][68];
    __shared__ float Bsm[64][68];
    for (int jj = tid; jj < 1024; jj += 256) {
        const int l = jj >> 4, k4 = (jj & 15) * 4;
        float4 v = make_float4(0.f, 0.f, 0.f, 0.f);
#pragma unroll
        for (int s = 0; s < kKS; s++) {
            float4 p = *(const float4*)&g_qallp[(size_t)s * (kL * kD) + (size_t)l * kD + kb + k4];
            v.x += p.x; v.y += p.y; v.z += p.z; v.w += p.w;
        }
        Asm[k4 + 0][l] = v.x; Asm[k4 + 1][l] = v.y;
        Asm[k4 + 2][l] = v.z; Asm[k4 + 3][l] = v.w;
    }
    for (int jj = tid; jj < 1024; jj += 256) {
        const int k = jj >> 4, e4 = (jj & 15) * 4;
        float4 v = *(const float4*)(Wk + (size_t)(kb + k) * kD + nt * 64 + e4);
        *(float4*)&Bsm[k][e4] = v;
    }
    __syncthreads();
    const int tx = tid & 15, ty = tid >> 4;
    float acc[4][4] = {};
#pragma unroll 4
    for (int k = 0; k < 64; k++) {
        float4 a = *(const float4*)&Asm[k][ty * 4];
        float4 b = *(const float4*)&Bsm[k][tx * 4];
        acc[0][0] += a.x * b.x; acc[0][1] += a.x * b.y; acc[0][2] += a.x * b.z; acc[0][3] += a.x * b.w;
        acc[1][0] += a.y * b.x; acc[1][1] += a.y * b.y; acc[1][2] += a.y * b.z; acc[1][3] += a.y * b.w;
        acc[2][0] += a.z * b.x; acc[2][1] += a.z * b.y; acc[2][2] += a.z * b.z; acc[2][3] += a.z * b.w;
        acc[3][0] += a.w * b.x; acc[3][1] += a.w * b.y; acc[3][2] += a.w * b.z; acc[3][3] += a.w * b.w;
    }
#pragma unroll
    for (int i = 0; i < 4; i++) {
        float4 v = make_float4(acc[i][0], acc[i][1], acc[i][2], acc[i][3]);
        *(float4*)&g_qkp[(size_t)(kz * kL + ty * 4 + i) * kD + nt * 64 + tx * 4] = v;
    }
}

// ============ K3: fused LN + logits + segment softmax (bf16-split out) ======
__global__ __launch_bounds__(256) void attn_k(const float* __restrict__ feats) {
    const int l = blockIdx.x, b = blockIdx.y;
    const int tid = threadIdx.x, wid = tid >> 5, lane = tid & 31;

    __shared__ float qk_s[kD];
    __shared__ float s_part[8][kD];
    __shared__ float den_part[8];

    for (int e = tid; e < kD; e += 256) {
        float s = 0.f;
#pragma unroll
        for (int ks = 0; ks < kKS; ks++) s += g_qkp[(size_t)(ks * kL + l) * kD + e];
        qk_s[e] = s;
    }
    __syncthreads();

    float4 qk4[4];
    float qks = 0.f;
#pragma unroll
    for (int q = 0; q < 4; q++) {
        qk4[q] = *(const float4*)&qk_s[(lane + 32 * q) * 4];
        qks += sum4(qk4[q]);
    }
#pragma unroll
    for (int o = 16; o; o >>= 1) qks += __shfl_xor_sync(0xffffffffu, qks, o);

    const int nv = g_nvalid[b];
    int segsz = nv / kL; if (segsz < 1) segsz = 1;
    const int n_used = min(nv, kL * segsz);
    const int t0 = l * segsz;
    const int t1 = min(t0 + segsz, n_used);

    float4 sac[4];
#pragma unroll
    for (int q = 0; q < 4; q++) sac[q] = make_float4(0.f, 0.f, 0.f, 0.f);
    float dac = 0.f;

    for (int t = t0 + wid; t < t1; t += 8) {
        const int orig = g_order[b * kN + t];
        const float4* row = (const float4*)(feats + ((size_t)b * kN + orig) * kD);
        float4 v[4];
        float sm = 0.f, sq = 0.f, dt = 0.f;
#pragma unroll
        for (int q = 0; q < 4; q++) {
            v[q] = row[lane + 32 * q];
            sm += sum4(v[q]);
            sq += dot4(v[q], v[q]);
            dt += dot4(v[q], qk4[q]);
        }
#pragma unroll
        for (int o = 16; o; o >>= 1) {
            sm += __shfl_xor_sync(0xffffffffu, sm, o);
            sq += __shfl_xor_sync(0xffffffffu, sq, o);
            dt += __shfl_xor_sync(0xffffffffu, dt, o);
        }
        const float mu = sm * (1.0f / kD);
        const float var = sq * (1.0f / kD) - mu * mu;
        const float rstd = rsqrtf(var + 1e-5f);
        float logit = (dt - mu * qks) * rstd * kInvTemp;
        logit = fminf(5.0f, fmaxf(-5.0f, logit));
        const float w = expf(logit - 5.0f);
        const float wr = w * rstd;
        const float wm = wr * mu;
#pragma unroll
        for (int q = 0; q < 4; q++) {
            sac[q].x += wr * v[q].x - wm;
            sac[q].y += wr * v[q].y - wm;
            sac[q].z += wr * v[q].z - wm;
            sac[q].w += wr * v[q].w - wm;
        }
        dac += w;
    }

#pragma unroll
    for (int q = 0; q < 4; q++)
        *(float4*)&s_part[wid][(lane + 32 * q) * 4] = sac[q];
    if (lane == 0) den_part[wid] = dac;
    __syncthreads();

    float den = 0.f;
#pragma unroll
    for (int w = 0; w < 8; w++) den += den_part[w];

    const int m = b * kL + l;
    const float inv = (den > 0.f) ? (1.0f / den) : 0.f;
    for (int e = tid; e < kD; e += 256) {
        float s = 0.f;
#pragma unroll
        for (int w = 0; w < 8; w++) s += s_part[w][e];
        const float v = s * inv;
        __nv_bfloat16 h = __float2bfloat16(v);
        g_Uh[(size_t)m * kD + e] = h;
        g_Ul[(size_t)m * kD + e] = __float2bfloat16(v - __bfloat162float(h));
    }
    if (tid == 0) g_denom[m] = den;
}

// ====== K4/K5: HMMA (mma.sync bf16) 3-term-split GEMM, 64x64 tile per CTA ===
// Effective D[m][n] = sum over K=1536: chunks 0-7 Ah*Bh, 8-15 Ah*Bl, 16-23 Al*Bh.
// EPI=1: Zattn epilogue (den>0 ? D : z) -> bf16 split into g_Zh/g_Zl.
// EPI=2: out = D + bo (nvalid==0 samples -> z rows), fp32.
template <int EPI>
__global__ __launch_bounds__(256) void hmma_k(const float* __restrict__ z,
                                              const float* __restrict__ bo,
                                              float* __restrict__ outp) {
    __shared__ __align__(16) uint8_t smA[2][8192];
    __shared__ __align__(16) uint8_t smB[2][8192];
    const int tid = threadIdx.x, wid = tid >> 5, lane = tid & 31;
    const int nt = blockIdx.x, mt = blockIdx.y;

    const __nv_bfloat16* Ahg = (EPI == 1) ? g_Uh : g_Zh;
    const __nv_bfloat16* Alg = (EPI == 1) ? g_Ul : g_Zl;
    const __nv_bfloat16* Bhg = (EPI == 1) ? g_Wvh : g_Woh;
    const __nv_bfloat16* Blg = (EPI == 1) ? g_Wvl : g_Wol;

    // loader: 2 x 16B chunks per thread per operand (rows lr0, lr0+32)
    const int lr0 = tid >> 3, lj = tid & 7;
    const int lr1 = lr0 + 32;
    const uint32_t sw0 = lr0 * 128 + ((lj ^ (lr0 & 7)) << 4);
    const uint32_t sw1 = lr1 * 128 + ((lj ^ (lr1 & 7)) << 4);

    // warp tile: 32m x 16n; ldmatrix per-thread source coords
    const int wm = (wid >> 2) << 5, wn = (wid & 3) << 4;
    const int a_r0 = wm + (lane & 15);
    const int a_r1 = a_r0 + 16;
    const int a_cadd = lane >> 4;                      // 0/1 -> k half
    const int b_r = wn + (lane & 7) + ((lane >> 4) << 3);
    const int b_cadd = (lane >> 3) & 1;
    const uint32_t smAu = s2u(smA), smBu = s2u(smB);

    float acc[2][2][4] = {};

    // chunk c (0..23): term t = c>>3, k-offset (c&7)*64
    const size_t mtoff = (size_t)(mt * 64) * kD;
    const size_t ntoff = (size_t)(nt * 64) * kD;

    uint4 ra0, ra1, rb0, rb1;
    {
        const __nv_bfloat16* a = Ahg + mtoff;
        const __nv_bfloat16* b = Bhg + ntoff;
        ra0 = *(const uint4*)(a + (size_t)lr0 * kD + lj * 8);
        ra1 = *(const uint4*)(a + (size_t)lr1 * kD + lj * 8);
        rb0 = *(const uint4*)(b + (size_t)lr0 * kD + lj * 8);
        rb1 = *(const uint4*)(b + (size_t)lr1 * kD + lj * 8);
    }
    *(uint4*)(smA[0] + sw0) = ra0; *(uint4*)(smA[0] + sw1) = ra1;
    *(uint4*)(smB[0] + sw0) = rb0; *(uint4*)(smB[0] + sw1) = rb1;
    __syncthreads();

    int buf = 0;
#pragma unroll 1
    for (int c = 0; c < 24; c++) {
        if (c < 23) {
            const int cn = c + 1;
            const int t = cn >> 3;
            const int kk = (cn & 7) * 64;
            const __nv_bfloat16* a = ((t < 2) ? Ahg : Alg) + mtoff + kk;
            const __nv_bfloat16* b = ((t == 1) ? Blg : Bhg) + ntoff + kk;
            ra0 = *(const uint4*)(a + (size_t)lr0 * kD + lj * 8);
            ra1 = *(const uint4*)(a + (size_t)lr1 * kD + lj * 8);
            rb0 = *(const uint4*)(b + (size_t)lr0 * kD + lj * 8);
            rb1 = *(const uint4*)(b + (size_t)lr1 * kD + lj * 8);
        }
        const uint32_t Abase = smAu + buf * 8192;
        const uint32_t Bbase = smBu + buf * 8192;
#pragma unroll
        for (int ks = 0; ks < 4; ks++) {
            uint32_t a0[4], a1[4], bb[4];
            const int ch = 2 * ks;
            const uint32_t adr0 = Abase + a_r0 * 128 + (((ch + a_cadd) ^ (a_r0 & 7)) << 4);
            const uint32_t adr1 = Abase + a_r1 * 128 + (((ch + a_cadd) ^ (a_r1 & 7)) << 4);
            const uint32_t bdr  = Bbase + b_r * 128 + (((ch + b_cadd) ^ (b_r & 7)) << 4);
            ldsm4(adr0, a0);
            ldsm4(adr1, a1);
            ldsm4(bdr, bb);
            mma16816(acc[0][0], a0, bb[0], bb[1]);
            mma16816(acc[0][1], a0, bb[2], bb[3]);
            mma16816(acc[1][0], a1, bb[0], bb[1]);
            mma16816(acc[1][1], a1, bb[2], bb[3]);
        }
        if (c < 23) {
            const int nb = buf ^ 1;
            *(uint4*)(smA[nb] + sw0) = ra0; *(uint4*)(smA[nb] + sw1) = ra1;
            *(uint4*)(smB[nb] + sw0) = rb0; *(uint4*)(smB[nb] + sw1) = rb1;
            __syncthreads();
            buf = nb;
        }
    }

    // epilogue: thread (g,tg) owns D rows {g,g+8} cols {tg*2,tg*2+1} per frag
    const int g = lane >> 2, tg = lane & 3;
#pragma unroll
    for (int mf = 0; mf < 2; mf++) {
#pragma unroll
        for (int rr = 0; rr < 2; rr++) {
            const int m = mt * 64 + wm + mf * 16 + g + rr * 8;
            const bool repl = (EPI == 1) ? (g_denom[m] <= 0.f) : (g_nvalid[m >> 6] == 0);
            const float* zr = z + (size_t)(m & (kL - 1)) * kD;
#pragma unroll
            for (int nf = 0; nf < 2; nf++) {
                const int n = nt * 64 + wn + nf * 8 + tg * 2;
                float v0 = acc[mf][nf][rr * 2 + 0];
                float v1 = acc[mf][nf][rr * 2 + 1];
                if (EPI == 1) {
                    if (repl) { v0 = zr[n]; v1 = zr[n + 1]; }
                    __nv_bfloat162 h = __floats2bfloat162_rn(v0, v1);
                    float2 hf = __bfloat1622float2(h);
                    __nv_bfloat162 lo = __floats2bfloat162_rn(v0 - hf.x, v1 - hf.y);
                    *(__nv_bfloat162*)(g_Zh + (size_t)m * kD + n) = h;
                    *(__nv_bfloat162*)(g_Zl + (size_t)m * kD + n) = lo;
                } else {
                    v0 += bo[n];
                    v1 += bo[n + 1];
                    if (repl) { v0 = zr[n]; v1 = zr[n + 1]; }
                    *(float2*)(outp + (size_t)m * kD + n) = make_float2(v0, v1);
                }
            }
        }
    }
}

// ---------------------------------------------------------------------------
extern "C" void kernel_launch(void* const* d_in, const int* in_sizes, int n_in,
                              void* d_out, int out_size) {
    (void)in_sizes; (void)n_in; (void)out_size;
    const float* feats = (const float*)d_in[0];
    // d_in[1] = coords (unused by the reference output)
    const void*  mask  = d_in[2];
    const float* z     = (const float*)d_in[3];
    const float* Wq    = (const float*)d_in[4];
    const float* Wk    = (const float*)d_in[5];
    const float* Wv    = (const float*)d_in[6];
    const float* Wo    = (const float*)d_in[7];
    const float* bo    = (const float*)d_in[8];
    float* out = (float*)d_out;

    k1_order_qall<<<kB + 64 + 128, 256>>>(mask, z, Wq, Wv, Wo);
    qk_gemm<<<64, 256>>>(Wk);
    attn_k<<<dim3(kL, kB), 256>>>(feats);
    hmma_k<1><<<dim3(8, 8), 256>>>(z, nullptr, nullptr);
    hmma_k<2><<<dim3(8, 8), 256>>>(z, bo, out);
}

// round 9
// speedup vs baseline: 1.4561x; 1.2361x over previous
#include <cuda_runtime.h>
#include <cuda_bf16.h>
#include <math.h>
#include <stdint.h>

namespace {
constexpr int kB = 8;
constexpr int kN = 4096;
constexpr int kD = 512;
constexpr int kL = 64;
constexpr int kKS = 8;                // split-k slices for qall/qk
constexpr int kM = kB * kL;           // 512 rows through the GEMMs
constexpr int kSlab = kM * kD;        // 262144 floats per partial slab
constexpr float kInvTemp = 0.044194173824159216f; // 1/sqrt(512)
constexpr int kStageBytes = 16384;    // 8KB A + 8KB B per stage
constexpr int kSmemDyn = 4 * kStageBytes;
}

// ---------------- scratch (device globals; no allocation allowed) ----------
__device__ int   g_order[kB * kN];
__device__ int   g_nvalid[kB];
__device__ float g_qallp[kKS * kL * kD];
__device__ float g_qkp[kKS * kL * kD];
__device__ float g_denom[kM];
__device__ __nv_bfloat16 g_Uh[kM * kD],  g_Ul[kM * kD];   // bf16 split of U
__device__ __nv_bfloat16 g_Wvh[kD * kD], g_Wvl[kD * kD];
__device__ __nv_bfloat16 g_Woh[kD * kD], g_Wol[kD * kD];
__device__ __nv_bfloat16 g_Zh[kM * kD],  g_Zl[kM * kD];   // bf16 split of Zattn
__device__ float g_GP[3 * kSlab];                          // term partial slabs

__device__ __forceinline__ float dot4(float4 a, float4 b) {
    return a.x * b.x + a.y * b.y + a.z * b.z + a.w * b.w;
}
__device__ __forceinline__ float sum4(float4 a) { return a.x + a.y + a.z + a.w; }

__device__ __forceinline__ bool mask_at(const void* m, int idx, int kind) {
    if (kind == 1) return ((const int*)m)[idx] != 0;
    if (kind == 2) return ((const float*)m)[idx] != 0.0f;
    return ((const unsigned char*)m)[idx] != 0;
}

__device__ __forceinline__ uint32_t s2u(const void* p) {
    uint32_t a;
    asm("{ .reg .u64 t; cvta.to.shared.u64 t, %1; cvt.u32.u64 %0, t; }"
        : "=r"(a) : "l"(p));
    return a;
}
__device__ __forceinline__ void ldsm4(uint32_t addr, uint32_t r[4]) {
    asm volatile("ldmatrix.sync.aligned.m8n8.x4.shared.b16 {%0,%1,%2,%3}, [%4];"
        : "=r"(r[0]), "=r"(r[1]), "=r"(r[2]), "=r"(r[3]) : "r"(addr));
}
__device__ __forceinline__ void mma16816(float d[4], const uint32_t a[4],
                                         uint32_t b0, uint32_t b1) {
    asm volatile(
        "mma.sync.aligned.m16n8k16.row.col.f32.bf16.bf16.f32 "
        "{%0,%1,%2,%3}, {%4,%5,%6,%7}, {%8,%9}, {%0,%1,%2,%3};"
        : "+f"(d[0]), "+f"(d[1]), "+f"(d[2]), "+f"(d[3])
        : "r"(a[0]), "r"(a[1]), "r"(a[2]), "r"(a[3]), "r"(b0), "r"(b1));
}
__device__ __forceinline__ void cp16(uint32_t saddr, const void* g) {
    asm volatile("cp.async.cg.shared.global [%0], [%1], 16;"
                 :: "r"(saddr), "l"(g) : "memory");
}
__device__ __forceinline__ void cp_commit() {
    asm volatile("cp.async.commit_group;" ::: "memory");
}
template <int N>
__device__ __forceinline__ void cp_wait() {
    asm volatile("cp.async.wait_group %0;" :: "n"(N) : "memory");
}

__device__ __forceinline__ void bf16_split_store4(float4 v, __nv_bfloat16* dh,
                                                  __nv_bfloat16* dl) {
    __nv_bfloat162 h01 = __floats2bfloat162_rn(v.x, v.y);
    __nv_bfloat162 h23 = __floats2bfloat162_rn(v.z, v.w);
    float2 f01 = __bfloat1622float2(h01);
    float2 f23 = __bfloat1622float2(h23);
    __nv_bfloat162 l01 = __floats2bfloat162_rn(v.x - f01.x, v.y - f01.y);
    __nv_bfloat162 l23 = __floats2bfloat162_rn(v.z - f23.x, v.w - f23.y);
    *(__nv_bfloat162*)(dh)     = h01;
    *(__nv_bfloat162*)(dh + 2) = h23;
    *(__nv_bfloat162*)(dl)     = l01;
    *(__nv_bfloat162*)(dl + 2) = l23;
}

// ==== K1: blocks 0..7 order; 8..71 qall tiles; 72..199 weight bf16 splits ===
__global__ __launch_bounds__(256) void k1_order_qall(const void* __restrict__ mask,
                                                     const float* __restrict__ z,
                                                     const float* __restrict__ Wq,
                                                     const float* __restrict__ Wv,
                                                     const float* __restrict__ Wo) {
    const int tid = threadIdx.x;
    const int wid = tid >> 5, lane = tid & 31;

    __shared__ float Asm[64][68];
    __shared__ float Bsm[64][68];

    if (blockIdx.x < kB) {
        const int b = blockIdx.x;
        const unsigned* mw = (const unsigned*)mask;
        int iok = 1, fok = 1;
        for (int i = tid; i < 1024; i += 256) {
            unsigned v = mw[b * 1024 + i];
            iok &= (v <= 1u);
            fok &= (v == 0u || v == 0x3F800000u);
        }
        iok = __syncthreads_and(iok);
        fok = __syncthreads_and(fok);
        const int kind = iok ? 1 : (fok ? 2 : 0);

        const int base = tid * 16;
        bool v[16];
        int c = 0;
#pragma unroll
        for (int j = 0; j < 16; j++) {
            v[j] = !mask_at(mask, b * kN + base + j, kind);
            c += v[j] ? 1 : 0;
        }
        int inc = c;
#pragma unroll
        for (int o = 1; o < 32; o <<= 1) {
            int x = __shfl_up_sync(0xffffffffu, inc, o);
            if (lane >= o) inc += x;
        }
        __shared__ int wsum[8], woff[8];
        if (lane == 31) wsum[wid] = inc;
        __syncthreads();
        if (tid < 8) {
            int s = 0;
            for (int w = 0; w < 8; w++) { woff[w] = s; s += wsum[w]; }
            if (tid == 0) g_nvalid[b] = s;
        }
        __syncthreads();
        int pos = woff[wid] + inc - c;
#pragma unroll
        for (int j = 0; j < 16; j++) {
            if (v[j]) g_order[b * kN + pos++] = base + j;
        }
    } else if (blockIdx.x < kB + 64) {
        const int bid2 = blockIdx.x - kB;
        const int nt = bid2 & 7, kz = bid2 >> 3;
        const int kb = kz * 64;
        for (int jj = tid; jj < 1024; jj += 256) {
            const int l = jj >> 4, k4 = (jj & 15) * 4;
            float4 v = *(const float4*)(z + (size_t)l * kD + kb + k4);
            Asm[k4 + 0][l] = v.x; Asm[k4 + 1][l] = v.y;
            Asm[k4 + 2][l] = v.z; Asm[k4 + 3][l] = v.w;
        }
        for (int jj = tid; jj < 1024; jj += 256) {
            const int d = jj >> 4, k4 = (jj & 15) * 4;
            float4 v = *(const float4*)(Wq + (size_t)(nt * 64 + d) * kD + kb + k4);
            Bsm[k4 + 0][d] = v.x; Bsm[k4 + 1][d] = v.y;
            Bsm[k4 + 2][d] = v.z; Bsm[k4 + 3][d] = v.w;
        }
        __syncthreads();
        const int tx = tid & 15, ty = tid >> 4;
        float acc[4][4] = {};
#pragma unroll 4
        for (int k = 0; k < 64; k++) {
            float4 a = *(const float4*)&Asm[k][ty * 4];
            float4 b = *(const float4*)&Bsm[k][tx * 4];
            acc[0][0] += a.x * b.x; acc[0][1] += a.x * b.y; acc[0][2] += a.x * b.z; acc[0][3] += a.x * b.w;
            acc[1][0] += a.y * b.x; acc[1][1] += a.y * b.y; acc[1][2] += a.y * b.z; acc[1][3] += a.y * b.w;
            acc[2][0] += a.z * b.x; acc[2][1] += a.z * b.y; acc[2][2] += a.z * b.z; acc[2][3] += a.z * b.w;
            acc[3][0] += a.w * b.x; acc[3][1] += a.w * b.y; acc[3][2] += a.w * b.z; acc[3][3] += a.w * b.w;
        }
#pragma unroll
        for (int i = 0; i < 4; i++) {
            float4 v = make_float4(acc[i][0], acc[i][1], acc[i][2], acc[i][3]);
            *(float4*)&g_qallp[(size_t)kz * (kL * kD) + (size_t)(ty * 4 + i) * kD + nt * 64 + tx * 4] = v;
        }
    } else {
        const int wb = blockIdx.x - (kB + 64);
        const int which = wb >> 6, lb = wb & 63;
        const float* src = which ? Wo : Wv;
        __nv_bfloat16* dh = which ? g_Woh : g_Wvh;
        __nv_bfloat16* dl = which ? g_Wol : g_Wvl;
#pragma unroll
        for (int it = 0; it < 4; it++) {
            const int i = lb * 4096 + it * 1024 + tid * 4;
            float4 v = *(const float4*)(src + i);
            bf16_split_store4(v, dh + i, dl + i);
        }
    }
}

// ======================= K2: qk GEMM ========================================
__global__ __launch_bounds__(256) void qk_gemm(const float* __restrict__ Wk) {
    const int tid = threadIdx.x;
    const int nt = blockIdx.x & 7, kz = blockIdx.x >> 3;
    const int kb = kz * 64;
    __shared__ float Asm[64][68];
    __shared__ float Bsm[64][68];
    for (int jj = tid; jj < 1024; jj += 256) {
        const int l = jj >> 4, k4 = (jj & 15) * 4;
        float4 v = make_float4(0.f, 0.f, 0.f, 0.f);
#pragma unroll
        for (int s = 0; s < kKS; s++) {
            float4 p = *(const float4*)&g_qallp[(size_t)s * (kL * kD) + (size_t)l * kD + kb + k4];
            v.x += p.x; v.y += p.y; v.z += p.z; v.w += p.w;
        }
        Asm[k4 + 0][l] = v.x; Asm[k4 + 1][l] = v.y;
        Asm[k4 + 2][l] = v.z; Asm[k4 + 3][l] = v.w;
    }
    for (int jj = tid; jj < 1024; jj += 256) {
        const int k = jj >> 4, e4 = (jj & 15) * 4;
        float4 v = *(const float4*)(Wk + (size_t)(kb + k) * kD + nt * 64 + e4);
        *(float4*)&Bsm[k][e4] = v;
    }
    __syncthreads();
    const int tx = tid & 15, ty = tid >> 4;
    float acc[4][4] = {};
#pragma unroll 4
    for (int k = 0; k < 64; k++) {
        float4 a = *(const float4*)&Asm[k][ty * 4];
        float4 b = *(const float4*)&Bsm[k][tx * 4];
        acc[0][0] += a.x * b.x; acc[0][1] += a.x * b.y; acc[0][2] += a.x * b.z; acc[0][3] += a.x * b.w;
        acc[1][0] += a.y * b.x; acc[1][1] += a.y * b.y; acc[1][2] += a.y * b.z; acc[1][3] += a.y * b.w;
        acc[2][0] += a.z * b.x; acc[2][1] += a.z * b.y; acc[2][2] += a.z * b.z; acc[2][3] += a.z * b.w;
        acc[3][0] += a.w * b.x; acc[3][1] += a.w * b.y; acc[3][2] += a.w * b.z; acc[3][3] += a.w * b.w;
    }
#pragma unroll
    for (int i = 0; i < 4; i++) {
        float4 v = make_float4(acc[i][0], acc[i][1], acc[i][2], acc[i][3]);
        *(float4*)&g_qkp[(size_t)(kz * kL + ty * 4 + i) * kD + nt * 64 + tx * 4] = v;
    }
}

// ============ K3: fused LN + logits + segment softmax (bf16-split out) ======
__global__ __launch_bounds__(256) void attn_k(const float* __restrict__ feats) {
    const int l = blockIdx.x, b = blockIdx.y;
    const int tid = threadIdx.x, wid = tid >> 5, lane = tid & 31;

    __shared__ float qk_s[kD];
    __shared__ float s_part[8][kD];
    __shared__ float den_part[8];

    for (int e = tid; e < kD; e += 256) {
        float s = 0.f;
#pragma unroll
        for (int ks = 0; ks < kKS; ks++) s += g_qkp[(size_t)(ks * kL + l) * kD + e];
        qk_s[e] = s;
    }
    __syncthreads();

    float4 qk4[4];
    float qks = 0.f;
#pragma unroll
    for (int q = 0; q < 4; q++) {
        qk4[q] = *(const float4*)&qk_s[(lane + 32 * q) * 4];
        qks += sum4(qk4[q]);
    }
#pragma unroll
    for (int o = 16; o; o >>= 1) qks += __shfl_xor_sync(0xffffffffu, qks, o);

    const int nv = g_nvalid[b];
    int segsz = nv / kL; if (segsz < 1) segsz = 1;
    const int n_used = min(nv, kL * segsz);
    const int t0 = l * segsz;
    const int t1 = min(t0 + segsz, n_used);

    float4 sac[4];
#pragma unroll
    for (int q = 0; q < 4; q++) sac[q] = make_float4(0.f, 0.f, 0.f, 0.f);
    float dac = 0.f;

    for (int t = t0 + wid; t < t1; t += 8) {
        const int orig = g_order[b * kN + t];
        const float4* row = (const float4*)(feats + ((size_t)b * kN + orig) * kD);
        float4 v[4];
        float sm = 0.f, sq = 0.f, dt = 0.f;
#pragma unroll
        for (int q = 0; q < 4; q++) {
            v[q] = row[lane + 32 * q];
            sm += sum4(v[q]);
            sq += dot4(v[q], v[q]);
            dt += dot4(v[q], qk4[q]);
        }
#pragma unroll
        for (int o = 16; o; o >>= 1) {
            sm += __shfl_xor_sync(0xffffffffu, sm, o);
            sq += __shfl_xor_sync(0xffffffffu, sq, o);
            dt += __shfl_xor_sync(0xffffffffu, dt, o);
        }
        const float mu = sm * (1.0f / kD);
        const float var = sq * (1.0f / kD) - mu * mu;
        const float rstd = rsqrtf(var + 1e-5f);
        float logit = (dt - mu * qks) * rstd * kInvTemp;
        logit = fminf(5.0f, fmaxf(-5.0f, logit));
        const float w = expf(logit - 5.0f);
        const float wr = w * rstd;
        const float wm = wr * mu;
#pragma unroll
        for (int q = 0; q < 4; q++) {
            sac[q].x += wr * v[q].x - wm;
            sac[q].y += wr * v[q].y - wm;
            sac[q].z += wr * v[q].z - wm;
            sac[q].w += wr * v[q].w - wm;
        }
        dac += w;
    }

#pragma unroll
    for (int q = 0; q < 4; q++)
        *(float4*)&s_part[wid][(lane + 32 * q) * 4] = sac[q];
    if (lane == 0) den_part[wid] = dac;
    __syncthreads();

    float den = 0.f;
#pragma unroll
    for (int w = 0; w < 8; w++) den += den_part[w];

    const int m = b * kL + l;
    const float inv = (den > 0.f) ? (1.0f / den) : 0.f;
    for (int e = tid; e < kD; e += 256) {
        float s = 0.f;
#pragma unroll
        for (int w = 0; w < 8; w++) s += s_part[w][e];
        const float v = s * inv;
        __nv_bfloat16 h = __float2bfloat16(v);
        g_Uh[(size_t)m * kD + e] = h;
        g_Ul[(size_t)m * kD + e] = __float2bfloat16(v - __bfloat162float(h));
    }
    if (tid == 0) g_denom[m] = den;
}

// ====== K4/K6: HMMA term-split GEMM — grid (8,8,3), cp.async 4-stage ========
// Term t: 0 -> Ah*Bh, 1 -> Ah*Bl, 2 -> Al*Bh, each K=512, partial into g_GP[t].
template <int G>
__global__ __launch_bounds__(256) void mma3_k() {
    extern __shared__ __align__(16) uint8_t sm[];   // 4 x (8KB A + 8KB B)
    const int tid = threadIdx.x, wid = tid >> 5, lane = tid & 31;
    const int nt = blockIdx.x, mt = blockIdx.y, t = blockIdx.z;

    const __nv_bfloat16* Ahg = (G == 1) ? g_Uh : g_Zh;
    const __nv_bfloat16* Alg = (G == 1) ? g_Ul : g_Zl;
    const __nv_bfloat16* Bhg = (G == 1) ? g_Wvh : g_Woh;
    const __nv_bfloat16* Blg = (G == 1) ? g_Wvl : g_Wol;
    const __nv_bfloat16* A = ((t < 2) ? Ahg : Alg) + (size_t)(mt * 64) * kD;
    const __nv_bfloat16* Bw = ((t == 1) ? Blg : Bhg) + (size_t)(nt * 64) * kD;

    // loader: 2x16B per operand per thread; rows lr0, lr0+32
    const int lr0 = tid >> 3, lj = tid & 7;
    const int lr1 = lr0 + 32;
    const uint32_t sw0 = lr0 * 128 + ((lj ^ (lr0 & 7)) << 4);
    const uint32_t sw1 = lr1 * 128 + ((lj ^ (lr1 & 7)) << 4);
    const uint32_t smu = s2u(sm);

    auto issue = [&](int c) {
        const uint32_t base = smu + (c & 3) * kStageBytes;
        const int kk = c * 64;
        cp16(base + sw0,        A  + (size_t)lr0 * kD + kk + lj * 8);
        cp16(base + sw1,        A  + (size_t)lr1 * kD + kk + lj * 8);
        cp16(base + 8192 + sw0, Bw + (size_t)lr0 * kD + kk + lj * 8);
        cp16(base + 8192 + sw1, Bw + (size_t)lr1 * kD + kk + lj * 8);
        cp_commit();
    };
    issue(0); issue(1); issue(2);

    // warp tile: 32m x 16n
    const int wm = (wid >> 2) << 5, wn = (wid & 3) << 4;
    const int a_r0 = wm + (lane & 15);
    const int a_r1 = a_r0 + 16;
    const int a_cadd = lane >> 4;
    const int b_r = wn + (lane & 7) + ((lane >> 4) << 3);
    const int b_cadd = (lane >> 3) & 1;

    float acc[2][2][4] = {};

#pragma unroll 1
    for (int c = 0; c < 8; c++) {
        cp_wait<2>();
        __syncthreads();
        const uint32_t Abase = smu + (c & 3) * kStageBytes;
        const uint32_t Bbase = Abase + 8192;
#pragma unroll
        for (int ks = 0; ks < 4; ks++) {
            uint32_t a0[4], a1[4], bb[4];
            const int ch = 2 * ks;
            const uint32_t adr0 = Abase + a_r0 * 128 + (((ch + a_cadd) ^ (a_r0 & 7)) << 4);
            const uint32_t adr1 = Abase + a_r1 * 128 + (((ch + a_cadd) ^ (a_r1 & 7)) << 4);
            const uint32_t bdr  = Bbase + b_r * 128 + (((ch + b_cadd) ^ (b_r & 7)) << 4);
            ldsm4(adr0, a0);
            ldsm4(adr1, a1);
            ldsm4(bdr, bb);
            mma16816(acc[0][0], a0, bb[0], bb[1]);
            mma16816(acc[0][1], a0, bb[2], bb[3]);
            mma16816(acc[1][0], a1, bb[0], bb[1]);
            mma16816(acc[1][1], a1, bb[2], bb[3]);
        }
        __syncthreads();     // all reads of stage c done before re-filling its buffer
        if (c + 3 < 8) issue(c + 3);
    }

    // store fp32 partial tile
    float* P = g_GP + (size_t)t * kSlab;
    const int g = lane >> 2, tg = lane & 3;
#pragma unroll
    for (int mf = 0; mf < 2; mf++) {
#pragma unroll
        for (int rr = 0; rr < 2; rr++) {
            const int m = mt * 64 + wm + mf * 16 + g + rr * 8;
#pragma unroll
            for (int nf = 0; nf < 2; nf++) {
                const int n = nt * 64 + wn + nf * 8 + tg * 2;
                *(float2*)(P + (size_t)m * kD + n) =
                    make_float2(acc[mf][nf][rr * 2 + 0], acc[mf][nf][rr * 2 + 1]);
            }
        }
    }
}

// ============ K5: reduce terms -> Zattn bf16 split (+ empty-seg repl) =======
__global__ __launch_bounds__(256) void reduce1_k(const float* __restrict__ z) {
    const int idx = blockIdx.x * 256 + threadIdx.x;  // float4 index
    const int m = idx >> 7, c4 = idx & 127;
    float4 v;
    if (g_denom[m] > 0.f) {
        float4 p0 = ((const float4*)g_GP)[idx];
        float4 p1 = ((const float4*)g_GP)[idx + kSlab / 4];
        float4 p2 = ((const float4*)g_GP)[idx + kSlab / 2];
        v = make_float4(p0.x + p1.x + p2.x, p0.y + p1.y + p2.y,
                        p0.z + p1.z + p2.z, p0.w + p1.w + p2.w);
    } else {
        v = ((const float4*)(z + (size_t)(m & (kL - 1)) * kD))[c4];
    }
    bf16_split_store4(v, g_Zh + idx * 4, g_Zl + idx * 4);
}

// ============ K7: final reduce + bias + sample replacement ==================
__global__ __launch_bounds__(256) void fin_k(float* __restrict__ out,
                                             const float* __restrict__ z,
                                             const float* __restrict__ bo) {
    const int idx = blockIdx.x * 256 + threadIdx.x;  // float4 index
    const int m = idx >> 7, c4 = idx & 127;
    float4 v;
    if (g_nvalid[m >> 6] == 0) {
        v = ((const float4*)(z + (size_t)(m & (kL - 1)) * kD))[c4];
    } else {
        float4 p0 = ((const float4*)g_GP)[idx];
        float4 p1 = ((const float4*)g_GP)[idx + kSlab / 4];
        float4 p2 = ((const float4*)g_GP)[idx + kSlab / 2];
        float4 b = ((const float4*)bo)[c4];
        v = make_float4(p0.x + p1.x + p2.x + b.x, p0.y + p1.y + p2.y + b.y,
                        p0.z + p1.z + p2.z + b.z, p0.w + p1.w + p2.w + b.w);
    }
    ((float4*)out)[idx] = v;
}

// ---------------------------------------------------------------------------
extern "C" void kernel_launch(void* const* d_in, const int* in_sizes, int n_in,
                              void* d_out, int out_size) {
    (void)in_sizes; (void)n_in; (void)out_size;
    const float* feats = (const float*)d_in[0];
    // d_in[1] = coords (unused by the reference output)
    const void*  mask  = d_in[2];
    const float* z     = (const float*)d_in[3];
    const float* Wq    = (const float*)d_in[4];
    const float* Wk    = (const float*)d_in[5];
    const float* Wv    = (const float*)d_in[6];
    const float* Wo    = (const float*)d_in[7];
    const float* bo    = (const float*)d_in[8];
    float* out = (float*)d_out;

    cudaFuncSetAttribute(mma3_k<1>, cudaFuncAttributeMaxDynamicSharedMemorySize, kSmemDyn);
    cudaFuncSetAttribute(mma3_k<2>, cudaFuncAttributeMaxDynamicSharedMemorySize, kSmemDyn);

    k1_order_qall<<<kB + 64 + 128, 256>>>(mask, z, Wq, Wv, Wo);
    qk_gemm<<<64, 256>>>(Wk);
    attn_k<<<dim3(kL, kB), 256>>>(feats);
    mma3_k<1><<<dim3(8, 8, 3), 256, kSmemDyn>>>();
    reduce1_k<<<kSlab / 4 / 256, 256>>>(z);
    mma3_k<2><<<dim3(8, 8, 3), 256, kSmemDyn>>>();
    fin_k<<<kSlab / 4 / 256, 256>>>(out, z, bo);
}

// round 10
// speedup vs baseline: 1.5300x; 1.0507x over previous
#include <cuda_runtime.h>
#include <cuda_bf16.h>
#include <math.h>
#include <stdint.h>

namespace {
constexpr int kB = 8;
constexpr int kN = 4096;
constexpr int kD = 512;
constexpr int kL = 64;
constexpr int kKS = 8;                // split-k slices for qall/qk
constexpr int kM = kB * kL;           // 512 rows through the GEMMs
constexpr int kSlab = kM * kD;        // 262144 floats per partial slab
constexpr int kNSlab = 6;             // term(3) x kz(2) partial slabs
constexpr float kInvTemp = 0.044194173824159216f; // 1/sqrt(512)
constexpr int kStageBytes = 16384;    // 8KB A + 8KB B per stage
constexpr int kSmemDyn = 4 * kStageBytes;
}

// ---------------- scratch (device globals; no allocation allowed) ----------
__device__ int   g_order[kB * kN];
__device__ int   g_nvalid[kB];
__device__ float g_qallp[kKS * kL * kD];
__device__ float g_qkp[kKS * kL * kD];
__device__ float g_denom[kM];
__device__ __nv_bfloat16 g_Uh[kM * kD],  g_Ul[kM * kD];   // bf16 split of U
__device__ __nv_bfloat16 g_Wvh[kD * kD], g_Wvl[kD * kD];
__device__ __nv_bfloat16 g_Woh[kD * kD], g_Wol[kD * kD];
__device__ __nv_bfloat16 g_Zh[kM * kD],  g_Zl[kM * kD];   // bf16 split of Zattn
__device__ float g_GP[kNSlab * kSlab];                     // partial slabs

__device__ __forceinline__ float dot4(float4 a, float4 b) {
    return a.x * b.x + a.y * b.y + a.z * b.z + a.w * b.w;
}
__device__ __forceinline__ float sum4(float4 a) { return a.x + a.y + a.z + a.w; }

__device__ __forceinline__ bool mask_at(const void* m, int idx, int kind) {
    if (kind == 1) return ((const int*)m)[idx] != 0;
    if (kind == 2) return ((const float*)m)[idx] != 0.0f;
    return ((const unsigned char*)m)[idx] != 0;
}

__device__ __forceinline__ uint32_t s2u(const void* p) {
    uint32_t a;
    asm("{ .reg .u64 t; cvta.to.shared.u64 t, %1; cvt.u32.u64 %0, t; }"
        : "=r"(a) : "l"(p));
    return a;
}
__device__ __forceinline__ void ldsm4(uint32_t addr, uint32_t r[4]) {
    asm volatile("ldmatrix.sync.aligned.m8n8.x4.shared.b16 {%0,%1,%2,%3}, [%4];"
        : "=r"(r[0]), "=r"(r[1]), "=r"(r[2]), "=r"(r[3]) : "r"(addr));
}
__device__ __forceinline__ void mma16816(float d[4], const uint32_t a[4],
                                         uint32_t b0, uint32_t b1) {
    asm volatile(
        "mma.sync.aligned.m16n8k16.row.col.f32.bf16.bf16.f32 "
        "{%0,%1,%2,%3}, {%4,%5,%6,%7}, {%8,%9}, {%0,%1,%2,%3};"
        : "+f"(d[0]), "+f"(d[1]), "+f"(d[2]), "+f"(d[3])
        : "r"(a[0]), "r"(a[1]), "r"(a[2]), "r"(a[3]), "r"(b0), "r"(b1));
}
__device__ __forceinline__ void cp16(uint32_t saddr, const void* g) {
    asm volatile("cp.async.cg.shared.global [%0], [%1], 16;"
                 :: "r"(saddr), "l"(g) : "memory");
}
__device__ __forceinline__ void cp_commit() {
    asm volatile("cp.async.commit_group;" ::: "memory");
}
template <int N>
__device__ __forceinline__ void cp_wait() {
    asm volatile("cp.async.wait_group %0;" :: "n"(N) : "memory");
}

__device__ __forceinline__ void bf16_split_store4(float4 v, __nv_bfloat16* dh,
                                                  __nv_bfloat16* dl) {
    __nv_bfloat162 h01 = __floats2bfloat162_rn(v.x, v.y);
    __nv_bfloat162 h23 = __floats2bfloat162_rn(v.z, v.w);
    float2 f01 = __bfloat1622float2(h01);
    float2 f23 = __bfloat1622float2(h23);
    __nv_bfloat162 l01 = __floats2bfloat162_rn(v.x - f01.x, v.y - f01.y);
    __nv_bfloat162 l23 = __floats2bfloat162_rn(v.z - f23.x, v.w - f23.y);
    *(__nv_bfloat162*)(dh)     = h01;
    *(__nv_bfloat162*)(dh + 2) = h23;
    *(__nv_bfloat162*)(dl)     = l01;
    *(__nv_bfloat162*)(dl + 2) = l23;
}

// ==== K1: blocks 0..7 order; 8..71 qall tiles; 72..199 weight bf16 splits ===
__global__ __launch_bounds__(256) void k1_order_qall(const void* __restrict__ mask,
                                                     const float* __restrict__ z,
                                                     const float* __restrict__ Wq,
                                                     const float* __restrict__ Wv,
                                                     const float* __restrict__ Wo) {
    const int tid = threadIdx.x;
    const int wid = tid >> 5, lane = tid & 31;

    __shared__ float Asm[64][68];
    __shared__ float Bsm[64][68];

    if (blockIdx.x < kB) {
        const int b = blockIdx.x;
        const unsigned* mw = (const unsigned*)mask;
        int iok = 1, fok = 1;
        for (int i = tid; i < 1024; i += 256) {
            unsigned v = mw[b * 1024 + i];
            iok &= (v <= 1u);
            fok &= (v == 0u || v == 0x3F800000u);
        }
        iok = __syncthreads_and(iok);
        fok = __syncthreads_and(fok);
        const int kind = iok ? 1 : (fok ? 2 : 0);

        const int base = tid * 16;
        bool v[16];
        int c = 0;
#pragma unroll
        for (int j = 0; j < 16; j++) {
            v[j] = !mask_at(mask, b * kN + base + j, kind);
            c += v[j] ? 1 : 0;
        }
        int inc = c;
#pragma unroll
        for (int o = 1; o < 32; o <<= 1) {
            int x = __shfl_up_sync(0xffffffffu, inc, o);
            if (lane >= o) inc += x;
        }
        __shared__ int wsum[8], woff[8];
        if (lane == 31) wsum[wid] = inc;
        __syncthreads();
        if (tid < 8) {
            int s = 0;
            for (int w = 0; w < 8; w++) { woff[w] = s; s += wsum[w]; }
            if (tid == 0) g_nvalid[b] = s;
        }
        __syncthreads();
        int pos = woff[wid] + inc - c;
#pragma unroll
        for (int j = 0; j < 16; j++) {
            if (v[j]) g_order[b * kN + pos++] = base + j;
        }
    } else if (blockIdx.x < kB + 64) {
        const int bid2 = blockIdx.x - kB;
        const int nt = bid2 & 7, kz = bid2 >> 3;
        const int kb = kz * 64;
        for (int jj = tid; jj < 1024; jj += 256) {
            const int l = jj >> 4, k4 = (jj & 15) * 4;
            float4 v = *(const float4*)(z + (size_t)l * kD + kb + k4);
            Asm[k4 + 0][l] = v.x; Asm[k4 + 1][l] = v.y;
            Asm[k4 + 2][l] = v.z; Asm[k4 + 3][l] = v.w;
        }
        for (int jj = tid; jj < 1024; jj += 256) {
            const int d = jj >> 4, k4 = (jj & 15) * 4;
            float4 v = *(const float4*)(Wq + (size_t)(nt * 64 + d) * kD + kb + k4);
            Bsm[k4 + 0][d] = v.x; Bsm[k4 + 1][d] = v.y;
            Bsm[k4 + 2][d] = v.z; Bsm[k4 + 3][d] = v.w;
        }
        __syncthreads();
        const int tx = tid & 15, ty = tid >> 4;
        float acc[4][4] = {};
#pragma unroll 4
        for (int k = 0; k < 64; k++) {
            float4 a = *(const float4*)&Asm[k][ty * 4];
            float4 b = *(const float4*)&Bsm[k][tx * 4];
            acc[0][0] += a.x * b.x; acc[0][1] += a.x * b.y; acc[0][2] += a.x * b.z; acc[0][3] += a.x * b.w;
            acc[1][0] += a.y * b.x; acc[1][1] += a.y * b.y; acc[1][2] += a.y * b.z; acc[1][3] += a.y * b.w;
            acc[2][0] += a.z * b.x; acc[2][1] += a.z * b.y; acc[2][2] += a.z * b.z; acc[2][3] += a.z * b.w;
            acc[3][0] += a.w * b.x; acc[3][1] += a.w * b.y; acc[3][2] += a.w * b.z; acc[3][3] += a.w * b.w;
        }
#pragma unroll
        for (int i = 0; i < 4; i++) {
            float4 v = make_float4(acc[i][0], acc[i][1], acc[i][2], acc[i][3]);
            *(float4*)&g_qallp[(size_t)kz * (kL * kD) + (size_t)(ty * 4 + i) * kD + nt * 64 + tx * 4] = v;
        }
    } else {
        const int wb = blockIdx.x - (kB + 64);
        const int which = wb >> 6, lb = wb & 63;
        const float* src = which ? Wo : Wv;
        __nv_bfloat16* dh = which ? g_Woh : g_Wvh;
        __nv_bfloat16* dl = which ? g_Wol : g_Wvl;
#pragma unroll
        for (int it = 0; it < 4; it++) {
            const int i = lb * 4096 + it * 1024 + tid * 4;
            float4 v = *(const float4*)(src + i);
            bf16_split_store4(v, dh + i, dl + i);
        }
    }
}

// ======================= K2: qk GEMM ========================================
__global__ __launch_bounds__(256) void qk_gemm(const float* __restrict__ Wk) {
    const int tid = threadIdx.x;
    const int nt = blockIdx.x & 7, kz = blockIdx.x >> 3;
    const int kb = kz * 64;
    __shared__ float Asm[64][68];
    __shared__ float Bsm[64][68];
    for (int jj = tid; jj < 1024; jj += 256) {
        const int l = jj >> 4, k4 = (jj & 15) * 4;
        float4 v = make_float4(0.f, 0.f, 0.f, 0.f);
#pragma unroll
        for (int s = 0; s < kKS; s++) {
            float4 p = *(const float4*)&g_qallp[(size_t)s * (kL * kD) + (size_t)l * kD + kb + k4];
            v.x += p.x; v.y += p.y; v.z += p.z; v.w += p.w;
        }
        Asm[k4 + 0][l] = v.x; Asm[k4 + 1][l] = v.y;
        Asm[k4 + 2][l] = v.z; Asm[k4 + 3][l] = v.w;
    }
    for (int jj = tid; jj < 1024; jj += 256) {
        const int k = jj >> 4, e4 = (jj & 15) * 4;
        float4 v = *(const float4*)(Wk + (size_t)(kb + k) * kD + nt * 64 + e4);
        *(float4*)&Bsm[k][e4] = v;
    }
    __syncthreads();
    const int tx = tid & 15, ty = tid >> 4;
    float acc[4][4] = {};
#pragma unroll 4
    for (int k = 0; k < 64; k++) {
        float4 a = *(const float4*)&Asm[k][ty * 4];
        float4 b = *(const float4*)&Bsm[k][tx * 4];
        acc[0][0] += a.x * b.x; acc[0][1] += a.x * b.y; acc[0][2] += a.x * b.z; acc[0][3] += a.x * b.w;
        acc[1][0] += a.y * b.x; acc[1][1] += a.y * b.y; acc[1][2] += a.y * b.z; acc[1][3] += a.y * b.w;
        acc[2][0] += a.z * b.x; acc[2][1] += a.z * b.y; acc[2][2] += a.z * b.z; acc[2][3] += a.z * b.w;
        acc[3][0] += a.w * b.x; acc[3][1] += a.w * b.y; acc[3][2] += a.w * b.z; acc[3][3] += a.w * b.w;
    }
#pragma unroll
    for (int i = 0; i < 4; i++) {
        float4 v = make_float4(acc[i][0], acc[i][1], acc[i][2], acc[i][3]);
        *(float4*)&g_qkp[(size_t)(kz * kL + ty * 4 + i) * kD + nt * 64 + tx * 4] = v;
    }
}

// ============ K3: fused LN + logits + segment softmax (bf16-split out) ======
__global__ __launch_bounds__(256) void attn_k(const float* __restrict__ feats) {
    const int l = blockIdx.x, b = blockIdx.y;
    const int tid = threadIdx.x, wid = tid >> 5, lane = tid & 31;

    __shared__ float qk_s[kD];
    __shared__ float s_part[8][kD];
    __shared__ float den_part[8];

    for (int e = tid; e < kD; e += 256) {
        float s = 0.f;
#pragma unroll
        for (int ks = 0; ks < kKS; ks++) s += g_qkp[(size_t)(ks * kL + l) * kD + e];
        qk_s[e] = s;
    }
    __syncthreads();

    float4 qk4[4];
    float qks = 0.f;
#pragma unroll
    for (int q = 0; q < 4; q++) {
        qk4[q] = *(const float4*)&qk_s[(lane + 32 * q) * 4];
        qks += sum4(qk4[q]);
    }
#pragma unroll
    for (int o = 16; o; o >>= 1) qks += __shfl_xor_sync(0xffffffffu, qks, o);

    const int nv = g_nvalid[b];
    int segsz = nv / kL; if (segsz < 1) segsz = 1;
    const int n_used = min(nv, kL * segsz);
    const int t0 = l * segsz;
    const int t1 = min(t0 + segsz, n_used);

    float4 sac[4];
#pragma unroll
    for (int q = 0; q < 4; q++) sac[q] = make_float4(0.f, 0.f, 0.f, 0.f);
    float dac = 0.f;

    // token loop with row + order prefetch (hides gather latency)
    int t = t0 + wid;
    int o_nxt = (t + 8 < t1) ? g_order[b * kN + t + 8] : 0;
    float4 v[4];
    if (t < t1) {
        const int o_cur = g_order[b * kN + t];
        const float4* row = (const float4*)(feats + ((size_t)b * kN + o_cur) * kD);
#pragma unroll
        for (int q = 0; q < 4; q++) v[q] = row[lane + 32 * q];
    }
    for (; t < t1; t += 8) {
        const int tn = t + 8;
        float4 vn[4];
        if (tn < t1) {
            const float4* rown = (const float4*)(feats + ((size_t)b * kN + o_nxt) * kD);
#pragma unroll
            for (int q = 0; q < 4; q++) vn[q] = rown[lane + 32 * q];
        }
        const int o_n2 = (tn + 8 < t1) ? g_order[b * kN + tn + 8] : 0;

        float sm = 0.f, sq = 0.f, dt = 0.f;
#pragma unroll
        for (int q = 0; q < 4; q++) {
            sm += sum4(v[q]);
            sq += dot4(v[q], v[q]);
            dt += dot4(v[q], qk4[q]);
        }
#pragma unroll
        for (int o = 16; o; o >>= 1) {
            sm += __shfl_xor_sync(0xffffffffu, sm, o);
            sq += __shfl_xor_sync(0xffffffffu, sq, o);
            dt += __shfl_xor_sync(0xffffffffu, dt, o);
        }
        const float mu = sm * (1.0f / kD);
        const float var = sq * (1.0f / kD) - mu * mu;
        const float rstd = rsqrtf(var + 1e-5f);
        float logit = (dt - mu * qks) * rstd * kInvTemp;
        logit = fminf(5.0f, fmaxf(-5.0f, logit));
        const float w = __expf(logit - 5.0f);
        const float wr = w * rstd;
        const float wm = wr * mu;
#pragma unroll
        for (int q = 0; q < 4; q++) {
            sac[q].x += wr * v[q].x - wm;
            sac[q].y += wr * v[q].y - wm;
            sac[q].z += wr * v[q].z - wm;
            sac[q].w += wr * v[q].w - wm;
        }
        dac += w;
        if (tn < t1) {
#pragma unroll
            for (int q = 0; q < 4; q++) v[q] = vn[q];
        }
        o_nxt = o_n2;
    }

#pragma unroll
    for (int q = 0; q < 4; q++)
        *(float4*)&s_part[wid][(lane + 32 * q) * 4] = sac[q];
    if (lane == 0) den_part[wid] = dac;
    __syncthreads();

    float den = 0.f;
#pragma unroll
    for (int w = 0; w < 8; w++) den += den_part[w];

    const int m = b * kL + l;
    const float inv = (den > 0.f) ? (1.0f / den) : 0.f;
    for (int e = tid; e < kD; e += 256) {
        float s = 0.f;
#pragma unroll
        for (int w = 0; w < 8; w++) s += s_part[w][e];
        const float v2 = s * inv;
        __nv_bfloat16 h = __float2bfloat16(v2);
        g_Uh[(size_t)m * kD + e] = h;
        g_Ul[(size_t)m * kD + e] = __float2bfloat16(v2 - __bfloat162float(h));
    }
    if (tid == 0) g_denom[m] = den;
}

// ====== K4/K6: HMMA term+K split GEMM — grid (8,8,6), fully prefetched ======
// z-slice s: term t = s>>1 (0 AhBh, 1 AhBl, 2 AlBh), kz = s&1 (K half).
// Each CTA: 64x64 tile, K=256 = 4 chunks, all 4 cp.async stages issued upfront.
template <int G>
__global__ __launch_bounds__(256) void mma3_k() {
    extern __shared__ __align__(16) uint8_t sm[];   // 4 x (8KB A + 8KB B)
    const int tid = threadIdx.x, wid = tid >> 5, lane = tid & 31;
    const int nt = blockIdx.x, mt = blockIdx.y, zs = blockIdx.z;
    const int t = zs >> 1, kz = zs & 1;

    const __nv_bfloat16* Ahg = (G == 1) ? g_Uh : g_Zh;
    const __nv_bfloat16* Alg = (G == 1) ? g_Ul : g_Zl;
    const __nv_bfloat16* Bhg = (G == 1) ? g_Wvh : g_Woh;
    const __nv_bfloat16* Blg = (G == 1) ? g_Wvl : g_Wol;
    const __nv_bfloat16* A = ((t < 2) ? Ahg : Alg) + (size_t)(mt * 64) * kD + kz * 256;
    const __nv_bfloat16* Bw = ((t == 1) ? Blg : Bhg) + (size_t)(nt * 64) * kD + kz * 256;

    // loader: 2x16B per operand per thread; rows lr0, lr0+32
    const int lr0 = tid >> 3, lj = tid & 7;
    const int lr1 = lr0 + 32;
    const uint32_t sw0 = lr0 * 128 + ((lj ^ (lr0 & 7)) << 4);
    const uint32_t sw1 = lr1 * 128 + ((lj ^ (lr1 & 7)) << 4);
    const uint32_t smu = s2u(sm);

#pragma unroll
    for (int c = 0; c < 4; c++) {
        const uint32_t base = smu + c * kStageBytes;
        const int kk = c * 64;
        cp16(base + sw0,        A  + (size_t)lr0 * kD + kk + lj * 8);
        cp16(base + sw1,        A  + (size_t)lr1 * kD + kk + lj * 8);
        cp16(base + 8192 + sw0, Bw + (size_t)lr0 * kD + kk + lj * 8);
        cp16(base + 8192 + sw1, Bw + (size_t)lr1 * kD + kk + lj * 8);
        cp_commit();
    }

    // warp tile: 32m x 16n
    const int wm = (wid >> 2) << 5, wn = (wid & 3) << 4;
    const int a_r0 = wm + (lane & 15);
    const int a_r1 = a_r0 + 16;
    const int a_cadd = lane >> 4;
    const int b_r = wn + (lane & 7) + ((lane >> 4) << 3);
    const int b_cadd = (lane >> 3) & 1;

    float acc[2][2][4] = {};

#pragma unroll
    for (int c = 0; c < 4; c++) {
        if (c == 0) cp_wait<3>();
        else if (c == 1) cp_wait<2>();
        else if (c == 2) cp_wait<1>();
        else cp_wait<0>();
        __syncthreads();
        const uint32_t Abase = smu + c * kStageBytes;
        const uint32_t Bbase = Abase + 8192;
#pragma unroll
        for (int ks = 0; ks < 4; ks++) {
            uint32_t a0[4], a1[4], bb[4];
            const int ch = 2 * ks;
            const uint32_t adr0 = Abase + a_r0 * 128 + (((ch + a_cadd) ^ (a_r0 & 7)) << 4);
            const uint32_t adr1 = Abase + a_r1 * 128 + (((ch + a_cadd) ^ (a_r1 & 7)) << 4);
            const uint32_t bdr  = Bbase + b_r * 128 + (((ch + b_cadd) ^ (b_r & 7)) << 4);
            ldsm4(adr0, a0);
            ldsm4(adr1, a1);
            ldsm4(bdr, bb);
            mma16816(acc[0][0], a0, bb[0], bb[1]);
            mma16816(acc[0][1], a0, bb[2], bb[3]);
            mma16816(acc[1][0], a1, bb[0], bb[1]);
            mma16816(acc[1][1], a1, bb[2], bb[3]);
        }
    }

    // store fp32 partial tile into slab zs
    float* P = g_GP + (size_t)zs * kSlab;
    const int g = lane >> 2, tg = lane & 3;
#pragma unroll
    for (int mf = 0; mf < 2; mf++) {
#pragma unroll
        for (int rr = 0; rr < 2; rr++) {
            const int m = mt * 64 + wm + mf * 16 + g + rr * 8;
#pragma unroll
            for (int nf = 0; nf < 2; nf++) {
                const int n = nt * 64 + wn + nf * 8 + tg * 2;
                *(float2*)(P + (size_t)m * kD + n) =
                    make_float2(acc[mf][nf][rr * 2 + 0], acc[mf][nf][rr * 2 + 1]);
            }
        }
    }
}

// ============ K5: reduce slabs -> Zattn bf16 split (+ empty-seg repl) =======
__global__ __launch_bounds__(256) void reduce1_k(const float* __restrict__ z) {
    const int idx = blockIdx.x * 256 + threadIdx.x;  // float4 index
    const int m = idx >> 7, c4 = idx & 127;
    float4 v;
    if (g_denom[m] > 0.f) {
        v = make_float4(0.f, 0.f, 0.f, 0.f);
#pragma unroll
        for (int s = 0; s < kNSlab; s++) {
            float4 p = ((const float4*)g_GP)[(size_t)s * (kSlab / 4) + idx];
            v.x += p.x; v.y += p.y; v.z += p.z; v.w += p.w;
        }
    } else {
        v = ((const float4*)(z + (size_t)(m & (kL - 1)) * kD))[c4];
    }
    bf16_split_store4(v, g_Zh + idx * 4, g_Zl + idx * 4);
}

// ============ K7: final reduce + bias + sample replacement ==================
__global__ __launch_bounds__(256) void fin_k(float* __restrict__ out,
                                             const float* __restrict__ z,
                                             const float* __restrict__ bo) {
    const int idx = blockIdx.x * 256 + threadIdx.x;  // float4 index
    const int m = idx >> 7, c4 = idx & 127;
    float4 v;
    if (g_nvalid[m >> 6] == 0) {
        v = ((const float4*)(z + (size_t)(m & (kL - 1)) * kD))[c4];
    } else {
        v = ((const float4*)bo)[c4];
#pragma unroll
        for (int s = 0; s < kNSlab; s++) {
            float4 p = ((const float4*)g_GP)[(size_t)s * (kSlab / 4) + idx];
            v.x += p.x; v.y += p.y; v.z += p.z; v.w += p.w;
        }
    }
    ((float4*)out)[idx] = v;
}

// ---------------------------------------------------------------------------
extern "C" void kernel_launch(void* const* d_in, const int* in_sizes, int n_in,
                              void* d_out, int out_size) {
    (void)in_sizes; (void)n_in; (void)out_size;
    const float* feats = (const float*)d_in[0];
    // d_in[1] = coords (unused by the reference output)
    const void*  mask  = d_in[2];
    const float* z     = (const float*)d_in[3];
    const float* Wq    = (const float*)d_in[4];
    const float* Wk    = (const float*)d_in[5];
    const float* Wv    = (const float*)d_in[6];
    const float* Wo    = (const float*)d_in[7];
    const float* bo    = (const float*)d_in[8];
    float* out = (float*)d_out;

    cudaFuncSetAttribute(mma3_k<1>, cudaFuncAttributeMaxDynamicSharedMemorySize, kSmemDyn);
    cudaFuncSetAttribute(mma3_k<2>, cudaFuncAttributeMaxDynamicSharedMemorySize, kSmemDyn);

    k1_order_qall<<<kB + 64 + 128, 256>>>(mask, z, Wq, Wv, Wo);
    qk_gemm<<<64, 256>>>(Wk);
    attn_k<<<dim3(kL, kB), 256>>>(feats);
    mma3_k<1><<<dim3(8, 8, 6), 256, kSmemDyn>>>();
    reduce1_k<<<kSlab / 4 / 256, 256>>>(z);
    mma3_k<2><<<dim3(8, 8, 6), 256, kSmemDyn>>>();
    fin_k<<<kSlab / 4 / 256, 256>>>(out, z, bo);
}